// round 12
// baseline (speedup 1.0000x reference)
#include <cuda_runtime.h>
#include <stdint.h>

#define NB 32
#define NC 4
#define NS 256
#define NL 256
#define NDIN 256
#define NDOUT 256

#define TAB_N 16384
#define TAB_SCALE 64.0f
#define TAB_H (1.0f / 64.0f)

__device__ float g_adj[NB * NS * NS];
__device__ float g_invdeg[NB * NS];
__device__ float g_Y[(size_t)NB * NC * NS * NDIN];
__device__ float2 g_tab[TAB_N + 1];

// ---------------------------------------------------------------------------
// Threefry-2x32, key=(0,42); partitionable XOR-fold bits (JAX >= 0.4.36)
// ---------------------------------------------------------------------------
__device__ __forceinline__ void threefry(uint32_t x0, uint32_t x1,
                                         uint32_t& o0, uint32_t& o1) {
  const uint32_t ks0 = 0u;
  const uint32_t ks1 = 42u;
  const uint32_t ks2 = 0u ^ 42u ^ 0x1BD11BDAu;
  x0 += ks0; x1 += ks1;
#define TF_R(r) { x0 += x1; x1 = __funnelshift_l(x1, x1, (r)); x1 ^= x0; }
  TF_R(13) TF_R(15) TF_R(26) TF_R(6)
  x0 += ks1; x1 += ks2 + 1u;
  TF_R(17) TF_R(29) TF_R(16) TF_R(24)
  x0 += ks2; x1 += ks0 + 2u;
  TF_R(13) TF_R(15) TF_R(26) TF_R(6)
  x0 += ks0; x1 += ks1 + 3u;
  TF_R(17) TF_R(29) TF_R(16) TF_R(24)
  x0 += ks1; x1 += ks2 + 4u;
  TF_R(13) TF_R(15) TF_R(26) TF_R(6)
  x0 += ks2; x1 += ks0 + 5u;
#undef TF_R
  o0 = x0; o1 = x1;
}

__device__ __forceinline__ uint32_t jax_bits(uint32_t p) {
  uint32_t o0, o1;
  threefry(0u, p, o0, o1);
  return o0 ^ o1;
}

__device__ __forceinline__ float bits_to_gumbel(uint32_t bits) {
  float f = __uint_as_float((bits >> 9) | 0x3F800000u) - 1.0f;
  float u = fmaxf(1e-10f, f + 1e-10f);
  return -logf(-logf(u));
}

__device__ __forceinline__ float gelu_exact(float x) {
  return 0.5f * x * (1.0f + erff(x * 0.70710678118654752440f));
}

// TF32 helpers
__device__ __forceinline__ uint32_t to_tf32(float x) {
  uint32_t r;
  asm("cvt.rna.tf32.f32 %0, %1;" : "=r"(r) : "f"(x));
  return r;
}
__device__ __forceinline__ void mma_tf32(float c[4],
    uint32_t a0, uint32_t a1, uint32_t a2, uint32_t a3,
    uint32_t b0, uint32_t b1) {
  asm volatile(
    "mma.sync.aligned.m16n8k8.row.col.f32.tf32.tf32.f32 "
    "{%0,%1,%2,%3}, {%4,%5,%6,%7}, {%8,%9}, {%0,%1,%2,%3};"
    : "+f"(c[0]), "+f"(c[1]), "+f"(c[2]), "+f"(c[3])
    : "r"(a0), "r"(a1), "r"(a2), "r"(a3), "r"(b0), "r"(b1));
}

// ---------------------------------------------------------------------------
// Exact MLP margin (fallback for |c| >= 128 — essentially never taken)
// ---------------------------------------------------------------------------
__device__ __forceinline__ void mlp_z(float c,
    const float* __restrict__ W1, const float* __restrict__ b1,
    const float* __restrict__ W2, const float* __restrict__ b2,
    const float* __restrict__ W3, const float* __restrict__ b3,
    float& z0, float& z1)
{
  float h1[16];
#pragma unroll
  for (int j = 0; j < 16; j++) h1[j] = gelu_exact(fmaf(c, W1[j], b1[j]));
  float h2[8];
#pragma unroll
  for (int k = 0; k < 8; k++) {
    float a = b2[k];
#pragma unroll
    for (int j = 0; j < 16; j++) a = fmaf(h1[j], W2[j * 8 + k], a);
    h2[k] = gelu_exact(a);
  }
  z0 = b3[0]; z1 = b3[1];
#pragma unroll
  for (int k = 0; k < 8; k++) {
    z0 = fmaf(h2[k], W3[2 * k + 0], z0);
    z1 = fmaf(h2[k], W3[2 * k + 1], z1);
  }
}

// ---------------------------------------------------------------------------
// Kernel 0: Hermite table of f(c)=z0-z1, f'(c)
// ---------------------------------------------------------------------------
__global__ void __launch_bounds__(256) build_tab_kernel(
    const float* __restrict__ W1, const float* __restrict__ b1,
    const float* __restrict__ W2, const float* __restrict__ b2,
    const float* __restrict__ W3, const float* __restrict__ b3)
{
  int i = blockIdx.x * blockDim.x + threadIdx.x;
  if (i > TAB_N) return;
  float c = (float)(i - TAB_N / 2) * TAB_H;

  float h1[16], dh1[16];
#pragma unroll
  for (int j = 0; j < 16; j++) {
    float a = fmaf(c, W1[j], b1[j]);
    float e = erff(a * 0.70710678118654752440f);
    float phi = 0.3989422804014327f * expf(-0.5f * a * a);
    h1[j]  = 0.5f * a * (1.0f + e);
    dh1[j] = (0.5f * (1.0f + e) + a * phi) * W1[j];
  }
  float h2[8], dh2[8];
#pragma unroll
  for (int k = 0; k < 8; k++) {
    float a = b2[k], da = 0.f;
#pragma unroll
    for (int j = 0; j < 16; j++) {
      a  = fmaf(h1[j],  W2[j * 8 + k], a);
      da = fmaf(dh1[j], W2[j * 8 + k], da);
    }
    float e = erff(a * 0.70710678118654752440f);
    float phi = 0.3989422804014327f * expf(-0.5f * a * a);
    h2[k]  = 0.5f * a * (1.0f + e);
    dh2[k] = (0.5f * (1.0f + e) + a * phi) * da;
  }
  float z0 = b3[0], z1 = b3[1], d0 = 0.f, d1 = 0.f;
#pragma unroll
  for (int k = 0; k < 8; k++) {
    z0 = fmaf(h2[k],  W3[2 * k + 0], z0);
    z1 = fmaf(h2[k],  W3[2 * k + 1], z1);
    d0 = fmaf(dh2[k], W3[2 * k + 0], d0);
    d1 = fmaf(dh2[k], W3[2 * k + 1], d1);
  }
  g_tab[i] = make_float2(z0 - z1, d0 - d1);
}

// ---------------------------------------------------------------------------
// Fast adjacency bit: spline margin + gumbel saturation skip
// ---------------------------------------------------------------------------
__device__ __forceinline__ float hard_bit_fast(float c, uint32_t q,
    const float* __restrict__ sW1, const float* __restrict__ sb1,
    const float* __restrict__ sW2, const float* __restrict__ sb2,
    const float* __restrict__ sW3, const float* __restrict__ sb3)
{
  float d;
  float u = fmaf(c, TAB_SCALE, (float)(TAB_N / 2));
  float fl = floorf(u);
  int i = (int)fl;
  if (i >= 0 && i < TAB_N) {
    float t = u - fl;
    float2 p0 = g_tab[i];
    float2 p1 = g_tab[i + 1];
    float m0 = p0.y * TAB_H, m1 = p1.y * TAB_H;
    float t2 = t * t, t3 = t2 * t;
    d = p0.x * (2.f * t3 - 3.f * t2 + 1.f) + m0 * (t3 - 2.f * t2 + t)
      + p1.x * (3.f * t2 - 2.f * t3)       + m1 * (t3 - t2);
  } else {
    float z0, z1;
    mlp_z(c, sW1, sb1, sW2, sb2, sW3, sb3, z0, z1);
    d = z0 - z1;
  }
  if (d >  19.5f) return 1.0f;
  if (d < -19.5f) return 0.0f;
  float g0 = bits_to_gumbel(jax_bits(2u * q));
  float g1 = bits_to_gumbel(jax_bits(2u * q + 1u));
  return (d + g0 >= g1) ? 1.0f : 0.0f;
}

// ---------------------------------------------------------------------------
// Kernel 1: adjacency bits (64x64 fp32 GEMM tile + fast epilogue)
// ---------------------------------------------------------------------------
__global__ void __launch_bounds__(256) adj_kernel(
    const float* __restrict__ fm,
    const float* __restrict__ W1, const float* __restrict__ b1,
    const float* __restrict__ W2, const float* __restrict__ b2,
    const float* __restrict__ W3, const float* __restrict__ b3)
{
  __shared__ float As[16][64];
  __shared__ float Bs[16][64];
  __shared__ float sW1[16], sb1[16], sW2[128], sb2[8], sW3[16], sb3[2];

  const int tid = threadIdx.x;
  const int b  = blockIdx.z;
  const int s0 = blockIdx.y * 64;
  const int t0 = blockIdx.x * 64;

  if (tid < 16)        sW1[tid]       = W1[tid];
  else if (tid < 32)   sb1[tid - 16]  = b1[tid - 16];
  else if (tid < 160)  sW2[tid - 32]  = W2[tid - 32];
  else if (tid < 168)  sb2[tid - 160] = b2[tid - 160];
  else if (tid < 184)  sW3[tid - 168] = W3[tid - 168];
  else if (tid < 186)  sb3[tid - 184] = b3[tid - 184];

  const float* A = fm + (size_t)b * NS * NL;
  const int lr = tid >> 2;
  const int lc = (tid & 3) << 2;
  const int ty = tid >> 4;
  const int tx = tid & 15;

  float acc[4][4];
#pragma unroll
  for (int i = 0; i < 4; i++)
#pragma unroll
    for (int j = 0; j < 4; j++) acc[i][j] = 0.f;

  for (int k0 = 0; k0 < NL; k0 += 16) {
    float4 av = *reinterpret_cast<const float4*>(A + (s0 + lr) * NL + k0 + lc);
    float4 bv = *reinterpret_cast<const float4*>(A + (t0 + lr) * NL + k0 + lc);
    __syncthreads();
    As[lc + 0][lr] = av.x; As[lc + 1][lr] = av.y; As[lc + 2][lr] = av.z; As[lc + 3][lr] = av.w;
    Bs[lc + 0][lr] = bv.x; Bs[lc + 1][lr] = bv.y; Bs[lc + 2][lr] = bv.z; Bs[lc + 3][lr] = bv.w;
    __syncthreads();
#pragma unroll
    for (int k = 0; k < 16; k++) {
      float4 a  = *reinterpret_cast<const float4*>(&As[k][ty << 2]);
      float4 bb = *reinterpret_cast<const float4*>(&Bs[k][tx << 2]);
      acc[0][0] = fmaf(a.x, bb.x, acc[0][0]); acc[0][1] = fmaf(a.x, bb.y, acc[0][1]);
      acc[0][2] = fmaf(a.x, bb.z, acc[0][2]); acc[0][3] = fmaf(a.x, bb.w, acc[0][3]);
      acc[1][0] = fmaf(a.y, bb.x, acc[1][0]); acc[1][1] = fmaf(a.y, bb.y, acc[1][1]);
      acc[1][2] = fmaf(a.y, bb.z, acc[1][2]); acc[1][3] = fmaf(a.y, bb.w, acc[1][3]);
      acc[2][0] = fmaf(a.z, bb.x, acc[2][0]); acc[2][1] = fmaf(a.z, bb.y, acc[2][1]);
      acc[2][2] = fmaf(a.z, bb.z, acc[2][2]); acc[2][3] = fmaf(a.z, bb.w, acc[2][3]);
      acc[3][0] = fmaf(a.w, bb.x, acc[3][0]); acc[3][1] = fmaf(a.w, bb.y, acc[3][1]);
      acc[3][2] = fmaf(a.w, bb.z, acc[3][2]); acc[3][3] = fmaf(a.w, bb.w, acc[3][3]);
    }
  }

#pragma unroll
  for (int i = 0; i < 4; i++) {
    int s = s0 + (ty << 2) + i;
#pragma unroll
    for (int j = 0; j < 4; j++) {
      int t = t0 + (tx << 2) + j;
      uint32_t q = ((uint32_t)b << 16) | ((uint32_t)s << 8) | (uint32_t)t;
      float bit;
      if (s == t) bit = 1.0f;
      else bit = hard_bit_fast(acc[i][j], q, sW1, sb1, sW2, sb2, sW3, sb3);
      g_adj[q] = bit;
    }
  }
}

// ---------------------------------------------------------------------------
// Kernel 2: inverse degree per row
// ---------------------------------------------------------------------------
__global__ void __launch_bounds__(256) invdeg_kernel() {
  int warp = (blockIdx.x * blockDim.x + threadIdx.x) >> 5;
  int lane = threadIdx.x & 31;
  if (warp >= NB * NS) return;
  const float* row = g_adj + (size_t)warp * NS;
  float s = 0.f;
#pragma unroll
  for (int t = lane; t < NS; t += 32) s += row[t];
#pragma unroll
  for (int o = 16; o; o >>= 1) s += __shfl_xor_sync(0xFFFFFFFFu, s, o);
  if (lane == 0) g_invdeg[warp] = 1.0f / s;
}

// ---------------------------------------------------------------------------
// TF32 tensor-core GEMM core with FRAGMENT-PACKED smem:
//   As4[mblk][gid][t4] = uint4{ a[m][k], a[m+8][k], a[m][k+4], a[m+8][k+4] }
//     (m = mblk*16+gid, k = t4)  -> one LDS.128 = full A fragment
//   Bs2[nblk][gid][t4] = uint2{ b[k=t4][n], b[k=t4+4][n] }  (n = nblk*8+gid)
//     -> one LDS.64 = full B fragment
// 8 vector LDS per warp per k-tile instead of 24 scalar LDS.
// ---------------------------------------------------------------------------

// A-tile writer: thread loads float4 of row `ar`, k = ac..ac+3; scatter into cells.
__device__ __forceinline__ void store_afrag(uint32_t* as_base, int ar, int ac,
                                            float4 av) {
  // cell word index = ((mblk*8 + g)*4 + t4)*4 + comp
  const int mblk = ar >> 4, g = ar & 7, half = (ar >> 3) & 1;
  const int comp = (ac ? 2 : 0) + half;
  uint32_t* cell = as_base + ((mblk * 8 + g) * 4) * 4 + comp;
  cell[0]  = to_tf32(av.x);
  cell[4]  = to_tf32(av.y);
  cell[8]  = to_tf32(av.z);
  cell[12] = to_tf32(av.w);
}

// B-tile writer: thread loads float4 of k-row `brow`, n = bcol..bcol+3.
__device__ __forceinline__ void store_bfrag(uint32_t* bs_base, int brow, int bcol,
                                            float4 bv) {
  const int t4b = brow & 3, compb = brow >> 2;
  const float v[4] = {bv.x, bv.y, bv.z, bv.w};
#pragma unroll
  for (int ii = 0; ii < 4; ii++) {
    int n = bcol + ii;
    // cell word index = ((nblk*8 + g)*4 + t4b)*2 + compb
    bs_base[(((n >> 3) * 8 + (n & 7)) * 4 + t4b) * 2 + compb] = to_tf32(v[ii]);
  }
}

// Kernel 3: Y[bc] = invdeg * (adj[b] @ F[bc])
__global__ void __launch_bounds__(256) prop_kernel(const float* __restrict__ features) {
  __shared__ uint4 As4[2][8][8][4];    // 8 KB
  __shared__ uint2 Bs2[2][16][8][4];   // 8 KB

  const int tid = threadIdx.x;
  const int bc = blockIdx.z;
  const int b  = bc >> 2;
  const int s0 = blockIdx.y * 128;
  const int d0 = blockIdx.x * 128;

  const float* A  = g_adj + (size_t)b * NS * NS;
  const float* Bm = features + (size_t)bc * NS * NDIN;

  const int ar = tid >> 1, ac = (tid & 1) << 2;
  const int brow = tid >> 5, bcol = (tid & 31) << 2;

  const int wid = tid >> 5, lane = tid & 31;
  const int wm = (wid >> 2) * 64, wn = (wid & 3) * 32;
  const int gid = lane >> 2, t4 = lane & 3;
  const int amblk0 = wm >> 4, bnblk0 = wn >> 3;

  float c[4][4][4];
#pragma unroll
  for (int i = 0; i < 4; i++)
#pragma unroll
    for (int j = 0; j < 4; j++)
#pragma unroll
      for (int r = 0; r < 4; r++) c[i][j][r] = 0.f;

  // preload tile 0
  {
    float4 av = *reinterpret_cast<const float4*>(A  + (s0 + ar) * NS + ac);
    float4 bv = *reinterpret_cast<const float4*>(Bm + brow * NDIN + d0 + bcol);
    store_afrag(reinterpret_cast<uint32_t*>(&As4[0][0][0][0]), ar, ac, av);
    store_bfrag(reinterpret_cast<uint32_t*>(&Bs2[0][0][0][0]), brow, bcol, bv);
  }
  __syncthreads();

  const int NK = NS / 8;
  for (int kt = 0; kt < NK; kt++) {
    const int cur = kt & 1;
    float4 av, bv;
    if (kt + 1 < NK) {
      int k0 = (kt + 1) * 8;
      av = *reinterpret_cast<const float4*>(A  + (s0 + ar) * NS + k0 + ac);
      bv = *reinterpret_cast<const float4*>(Bm + (k0 + brow) * NDIN + d0 + bcol);
    }
    uint4 afr[4];
    uint2 bfr[4];
#pragma unroll
    for (int i = 0; i < 4; i++) afr[i] = As4[cur][amblk0 + i][gid][t4];
#pragma unroll
    for (int j = 0; j < 4; j++) bfr[j] = Bs2[cur][bnblk0 + j][gid][t4];
#pragma unroll
    for (int i = 0; i < 4; i++)
#pragma unroll
      for (int j = 0; j < 4; j++)
        mma_tf32(c[i][j], afr[i].x, afr[i].y, afr[i].z, afr[i].w,
                 bfr[j].x, bfr[j].y);
    if (kt + 1 < NK) {
      const int nxt = 1 - cur;
      store_afrag(reinterpret_cast<uint32_t*>(&As4[nxt][0][0][0]), ar, ac, av);
      store_bfrag(reinterpret_cast<uint32_t*>(&Bs2[nxt][0][0][0]), brow, bcol, bv);
      __syncthreads();
    }
  }

#pragma unroll
  for (int i = 0; i < 4; i++) {
    int r0 = s0 + wm + i * 16 + gid;
    int r1 = r0 + 8;
    float sc0 = g_invdeg[b * NS + r0];
    float sc1 = g_invdeg[b * NS + r1];
#pragma unroll
    for (int j = 0; j < 4; j++) {
      int col = d0 + wn + j * 8 + 2 * t4;
      float* p0 = &g_Y[((size_t)bc * NS + r0) * NDIN + col];
      float* p1 = &g_Y[((size_t)bc * NS + r1) * NDIN + col];
      *reinterpret_cast<float2*>(p0) = make_float2(sc0 * c[i][j][0], sc0 * c[i][j][1]);
      *reinterpret_cast<float2*>(p1) = make_float2(sc1 * c[i][j][2], sc1 * c[i][j][3]);
    }
  }
}

// Kernel 4: out = Y @ Wl + bl   (32768 x 256 x 256, tf32 MMA)
__global__ void __launch_bounds__(256) out_kernel(const float* __restrict__ Wl,
                                                  const float* __restrict__ bl,
                                                  float* __restrict__ out) {
  __shared__ uint4 As4[2][8][8][4];
  __shared__ uint2 Bs2[2][16][8][4];

  const int tid = threadIdx.x;
  const int m0 = blockIdx.y * 128;
  const int n0 = blockIdx.x * 128;

  const int ar = tid >> 1, ac = (tid & 1) << 2;
  const int brow = tid >> 5, bcol = (tid & 31) << 2;

  const int wid = tid >> 5, lane = tid & 31;
  const int wm = (wid >> 2) * 64, wn = (wid & 3) * 32;
  const int gid = lane >> 2, t4 = lane & 3;
  const int amblk0 = wm >> 4, bnblk0 = wn >> 3;

  float c[4][4][4];
#pragma unroll
  for (int i = 0; i < 4; i++)
#pragma unroll
    for (int j = 0; j < 4; j++)
#pragma unroll
      for (int r = 0; r < 4; r++) c[i][j][r] = 0.f;

  {
    float4 av = *reinterpret_cast<const float4*>(&g_Y[(size_t)(m0 + ar) * NDIN + ac]);
    float4 bv = *reinterpret_cast<const float4*>(Wl + brow * NDOUT + n0 + bcol);
    store_afrag(reinterpret_cast<uint32_t*>(&As4[0][0][0][0]), ar, ac, av);
    store_bfrag(reinterpret_cast<uint32_t*>(&Bs2[0][0][0][0]), brow, bcol, bv);
  }
  __syncthreads();

  const int NK = NDIN / 8;
  for (int kt = 0; kt < NK; kt++) {
    const int cur = kt & 1;
    float4 av, bv;
    if (kt + 1 < NK) {
      int k0 = (kt + 1) * 8;
      av = *reinterpret_cast<const float4*>(&g_Y[(size_t)(m0 + ar) * NDIN + k0 + ac]);
      bv = *reinterpret_cast<const float4*>(Wl + (k0 + brow) * NDOUT + n0 + bcol);
    }
    uint4 afr[4];
    uint2 bfr[4];
#pragma unroll
    for (int i = 0; i < 4; i++) afr[i] = As4[cur][amblk0 + i][gid][t4];
#pragma unroll
    for (int j = 0; j < 4; j++) bfr[j] = Bs2[cur][bnblk0 + j][gid][t4];
#pragma unroll
    for (int i = 0; i < 4; i++)
#pragma unroll
      for (int j = 0; j < 4; j++)
        mma_tf32(c[i][j], afr[i].x, afr[i].y, afr[i].z, afr[i].w,
                 bfr[j].x, bfr[j].y);
    if (kt + 1 < NK) {
      const int nxt = 1 - cur;
      store_afrag(reinterpret_cast<uint32_t*>(&As4[nxt][0][0][0]), ar, ac, av);
      store_bfrag(reinterpret_cast<uint32_t*>(&Bs2[nxt][0][0][0]), brow, bcol, bv);
      __syncthreads();
    }
  }

#pragma unroll
  for (int i = 0; i < 4; i++) {
    int r0 = m0 + wm + i * 16 + gid;
    int r1 = r0 + 8;
#pragma unroll
    for (int j = 0; j < 4; j++) {
      int col = n0 + wn + j * 8 + 2 * t4;
      float2 bias = *reinterpret_cast<const float2*>(bl + col);
      float* p0 = &out[(size_t)r0 * NDOUT + col];
      float* p1 = &out[(size_t)r1 * NDOUT + col];
      *reinterpret_cast<float2*>(p0) = make_float2(c[i][j][0] + bias.x, c[i][j][1] + bias.y);
      *reinterpret_cast<float2*>(p1) = make_float2(c[i][j][2] + bias.x, c[i][j][3] + bias.y);
    }
  }
}

// ---------------------------------------------------------------------------
extern "C" void kernel_launch(void* const* d_in, const int* in_sizes, int n_in,
                              void* d_out, int out_size) {
  const float *features = 0, *fm = 0, *W1 = 0, *b1 = 0, *W2 = 0, *b2 = 0,
              *W3 = 0, *b3 = 0, *Wl = 0, *bl = 0;
  int n16 = 0;
  for (int i = 0; i < n_in; i++) {
    const float* p = (const float*)d_in[i];
    switch (in_sizes[i]) {
      case 8388608: features = p; break;
      case 2097152: fm = p; break;
      case 128:     W2 = p; break;
      case 8:       b2 = p; break;
      case 2:       b3 = p; break;
      case 65536:   Wl = p; break;
      case 256:     bl = p; break;
      case 16:
        if (n16 == 0) W1 = p; else if (n16 == 1) b1 = p; else W3 = p;
        n16++; break;
      default: break;
    }
  }
  float* out = (float*)d_out;

  build_tab_kernel<<<(TAB_N + 256) / 256, 256>>>(W1, b1, W2, b2, W3, b3);
  adj_kernel<<<dim3(4, 4, 32), 256>>>(fm, W1, b1, W2, b2, W3, b3);
  invdeg_kernel<<<(NB * NS) / 8, 256>>>();
  prop_kernel<<<dim3(2, 2, 128), 256>>>(features);
  out_kernel<<<dim3(2, 256, 1), 256>>>(Wl, bl, out);
}

// round 13
// speedup vs baseline: 1.4930x; 1.4930x over previous
#include <cuda_runtime.h>
#include <stdint.h>

#define NB 32
#define NC 4
#define NS 256
#define NL 256
#define NDIN 256
#define NDOUT 256

#define TAB_N 16384
#define TAB_SCALE 64.0f
#define TAB_H (1.0f / 64.0f)

__device__ float g_adj[NB * NS * NS];
__device__ float g_deg[NB * NS];                      // exact integer row degrees
__device__ float g_Y[(size_t)NB * NC * NS * NDIN];
__device__ float2 g_tab[TAB_N + 1];

// ---------------------------------------------------------------------------
// Threefry-2x32, key=(0,42); partitionable XOR-fold bits (JAX >= 0.4.36)
// ---------------------------------------------------------------------------
__device__ __forceinline__ void threefry(uint32_t x0, uint32_t x1,
                                         uint32_t& o0, uint32_t& o1) {
  const uint32_t ks0 = 0u;
  const uint32_t ks1 = 42u;
  const uint32_t ks2 = 0u ^ 42u ^ 0x1BD11BDAu;
  x0 += ks0; x1 += ks1;
#define TF_R(r) { x0 += x1; x1 = __funnelshift_l(x1, x1, (r)); x1 ^= x0; }
  TF_R(13) TF_R(15) TF_R(26) TF_R(6)
  x0 += ks1; x1 += ks2 + 1u;
  TF_R(17) TF_R(29) TF_R(16) TF_R(24)
  x0 += ks2; x1 += ks0 + 2u;
  TF_R(13) TF_R(15) TF_R(26) TF_R(6)
  x0 += ks0; x1 += ks1 + 3u;
  TF_R(17) TF_R(29) TF_R(16) TF_R(24)
  x0 += ks1; x1 += ks2 + 4u;
  TF_R(13) TF_R(15) TF_R(26) TF_R(6)
  x0 += ks2; x1 += ks0 + 5u;
#undef TF_R
  o0 = x0; o1 = x1;
}

__device__ __forceinline__ uint32_t jax_bits(uint32_t p) {
  uint32_t o0, o1;
  threefry(0u, p, o0, o1);
  return o0 ^ o1;
}

__device__ __forceinline__ float bits_to_gumbel(uint32_t bits) {
  float f = __uint_as_float((bits >> 9) | 0x3F800000u) - 1.0f;
  float u = fmaxf(1e-10f, f + 1e-10f);
  return -logf(-logf(u));
}

__device__ __forceinline__ float gelu_exact(float x) {
  return 0.5f * x * (1.0f + erff(x * 0.70710678118654752440f));
}

// TF32 helpers
__device__ __forceinline__ uint32_t to_tf32(float x) {
  uint32_t r;
  asm("cvt.rna.tf32.f32 %0, %1;" : "=r"(r) : "f"(x));
  return r;
}
__device__ __forceinline__ void mma_tf32(float c[4],
    uint32_t a0, uint32_t a1, uint32_t a2, uint32_t a3,
    uint32_t b0, uint32_t b1) {
  asm volatile(
    "mma.sync.aligned.m16n8k8.row.col.f32.tf32.tf32.f32 "
    "{%0,%1,%2,%3}, {%4,%5,%6,%7}, {%8,%9}, {%0,%1,%2,%3};"
    : "+f"(c[0]), "+f"(c[1]), "+f"(c[2]), "+f"(c[3])
    : "r"(a0), "r"(a1), "r"(a2), "r"(a3), "r"(b0), "r"(b1));
}

// ---------------------------------------------------------------------------
// Exact MLP margin (fallback for |c| >= 128 — essentially never taken)
// ---------------------------------------------------------------------------
__device__ __forceinline__ void mlp_z(float c,
    const float* __restrict__ W1, const float* __restrict__ b1,
    const float* __restrict__ W2, const float* __restrict__ b2,
    const float* __restrict__ W3, const float* __restrict__ b3,
    float& z0, float& z1)
{
  float h1[16];
#pragma unroll
  for (int j = 0; j < 16; j++) h1[j] = gelu_exact(fmaf(c, W1[j], b1[j]));
  float h2[8];
#pragma unroll
  for (int k = 0; k < 8; k++) {
    float a = b2[k];
#pragma unroll
    for (int j = 0; j < 16; j++) a = fmaf(h1[j], W2[j * 8 + k], a);
    h2[k] = gelu_exact(a);
  }
  z0 = b3[0]; z1 = b3[1];
#pragma unroll
  for (int k = 0; k < 8; k++) {
    z0 = fmaf(h2[k], W3[2 * k + 0], z0);
    z1 = fmaf(h2[k], W3[2 * k + 1], z1);
  }
}

// ---------------------------------------------------------------------------
// Kernel 0: Hermite table of f(c)=z0-z1, f'(c); also zeroes g_deg
// ---------------------------------------------------------------------------
__global__ void __launch_bounds__(256) build_tab_kernel(
    const float* __restrict__ W1, const float* __restrict__ b1,
    const float* __restrict__ W2, const float* __restrict__ b2,
    const float* __restrict__ W3, const float* __restrict__ b3)
{
  int i = blockIdx.x * blockDim.x + threadIdx.x;
  if (i < NB * NS) g_deg[i] = 0.f;        // reset degrees every launch
  if (i > TAB_N) return;
  float c = (float)(i - TAB_N / 2) * TAB_H;

  float h1[16], dh1[16];
#pragma unroll
  for (int j = 0; j < 16; j++) {
    float a = fmaf(c, W1[j], b1[j]);
    float e = erff(a * 0.70710678118654752440f);
    float phi = 0.3989422804014327f * expf(-0.5f * a * a);
    h1[j]  = 0.5f * a * (1.0f + e);
    dh1[j] = (0.5f * (1.0f + e) + a * phi) * W1[j];
  }
  float h2[8], dh2[8];
#pragma unroll
  for (int k = 0; k < 8; k++) {
    float a = b2[k], da = 0.f;
#pragma unroll
    for (int j = 0; j < 16; j++) {
      a  = fmaf(h1[j],  W2[j * 8 + k], a);
      da = fmaf(dh1[j], W2[j * 8 + k], da);
    }
    float e = erff(a * 0.70710678118654752440f);
    float phi = 0.3989422804014327f * expf(-0.5f * a * a);
    h2[k]  = 0.5f * a * (1.0f + e);
    dh2[k] = (0.5f * (1.0f + e) + a * phi) * da;
  }
  float z0 = b3[0], z1 = b3[1], d0 = 0.f, d1 = 0.f;
#pragma unroll
  for (int k = 0; k < 8; k++) {
    z0 = fmaf(h2[k],  W3[2 * k + 0], z0);
    z1 = fmaf(h2[k],  W3[2 * k + 1], z1);
    d0 = fmaf(dh2[k], W3[2 * k + 0], d0);
    d1 = fmaf(dh2[k], W3[2 * k + 1], d1);
  }
  g_tab[i] = make_float2(z0 - z1, d0 - d1);
}

// ---------------------------------------------------------------------------
// Fast adjacency bit: spline margin + gumbel saturation skip
// ---------------------------------------------------------------------------
__device__ __forceinline__ float hard_bit_fast(float c, uint32_t q,
    const float* __restrict__ sW1, const float* __restrict__ sb1,
    const float* __restrict__ sW2, const float* __restrict__ sb2,
    const float* __restrict__ sW3, const float* __restrict__ sb3)
{
  float d;
  float u = fmaf(c, TAB_SCALE, (float)(TAB_N / 2));
  float fl = floorf(u);
  int i = (int)fl;
  if (i >= 0 && i < TAB_N) {
    float t = u - fl;
    float2 p0 = g_tab[i];
    float2 p1 = g_tab[i + 1];
    float m0 = p0.y * TAB_H, m1 = p1.y * TAB_H;
    float t2 = t * t, t3 = t2 * t;
    d = p0.x * (2.f * t3 - 3.f * t2 + 1.f) + m0 * (t3 - 2.f * t2 + t)
      + p1.x * (3.f * t2 - 2.f * t3)       + m1 * (t3 - t2);
  } else {
    float z0, z1;
    mlp_z(c, sW1, sb1, sW2, sb2, sW3, sb3, z0, z1);
    d = z0 - z1;
  }
  if (d >  19.5f) return 1.0f;
  if (d < -19.5f) return 0.0f;
  float g0 = bits_to_gumbel(jax_bits(2u * q));
  float g1 = bits_to_gumbel(jax_bits(2u * q + 1u));
  return (d + g0 >= g1) ? 1.0f : 0.0f;
}

// ---------------------------------------------------------------------------
// Kernel 1: adjacency bits (64x64 fp32 GEMM tile + fast epilogue) with fused
// degree accumulation (shfl-reduce over the 16 tx lanes, one atomicAdd/row).
// ---------------------------------------------------------------------------
__global__ void __launch_bounds__(256) adj_kernel(
    const float* __restrict__ fm,
    const float* __restrict__ W1, const float* __restrict__ b1,
    const float* __restrict__ W2, const float* __restrict__ b2,
    const float* __restrict__ W3, const float* __restrict__ b3)
{
  __shared__ float As[16][64];
  __shared__ float Bs[16][64];
  __shared__ float sW1[16], sb1[16], sW2[128], sb2[8], sW3[16], sb3[2];

  const int tid = threadIdx.x;
  const int b  = blockIdx.z;
  const int s0 = blockIdx.y * 64;
  const int t0 = blockIdx.x * 64;

  if (tid < 16)        sW1[tid]       = W1[tid];
  else if (tid < 32)   sb1[tid - 16]  = b1[tid - 16];
  else if (tid < 160)  sW2[tid - 32]  = W2[tid - 32];
  else if (tid < 168)  sb2[tid - 160] = b2[tid - 160];
  else if (tid < 184)  sW3[tid - 168] = W3[tid - 168];
  else if (tid < 186)  sb3[tid - 184] = b3[tid - 184];

  const float* A = fm + (size_t)b * NS * NL;
  const int lr = tid >> 2;
  const int lc = (tid & 3) << 2;
  const int ty = tid >> 4;
  const int tx = tid & 15;

  float acc[4][4];
#pragma unroll
  for (int i = 0; i < 4; i++)
#pragma unroll
    for (int j = 0; j < 4; j++) acc[i][j] = 0.f;

  for (int k0 = 0; k0 < NL; k0 += 16) {
    float4 av = *reinterpret_cast<const float4*>(A + (s0 + lr) * NL + k0 + lc);
    float4 bv = *reinterpret_cast<const float4*>(A + (t0 + lr) * NL + k0 + lc);
    __syncthreads();
    As[lc + 0][lr] = av.x; As[lc + 1][lr] = av.y; As[lc + 2][lr] = av.z; As[lc + 3][lr] = av.w;
    Bs[lc + 0][lr] = bv.x; Bs[lc + 1][lr] = bv.y; Bs[lc + 2][lr] = bv.z; Bs[lc + 3][lr] = bv.w;
    __syncthreads();
#pragma unroll
    for (int k = 0; k < 16; k++) {
      float4 a  = *reinterpret_cast<const float4*>(&As[k][ty << 2]);
      float4 bb = *reinterpret_cast<const float4*>(&Bs[k][tx << 2]);
      acc[0][0] = fmaf(a.x, bb.x, acc[0][0]); acc[0][1] = fmaf(a.x, bb.y, acc[0][1]);
      acc[0][2] = fmaf(a.x, bb.z, acc[0][2]); acc[0][3] = fmaf(a.x, bb.w, acc[0][3]);
      acc[1][0] = fmaf(a.y, bb.x, acc[1][0]); acc[1][1] = fmaf(a.y, bb.y, acc[1][1]);
      acc[1][2] = fmaf(a.y, bb.z, acc[1][2]); acc[1][3] = fmaf(a.y, bb.w, acc[1][3]);
      acc[2][0] = fmaf(a.z, bb.x, acc[2][0]); acc[2][1] = fmaf(a.z, bb.y, acc[2][1]);
      acc[2][2] = fmaf(a.z, bb.z, acc[2][2]); acc[2][3] = fmaf(a.z, bb.w, acc[2][3]);
      acc[3][0] = fmaf(a.w, bb.x, acc[3][0]); acc[3][1] = fmaf(a.w, bb.y, acc[3][1]);
      acc[3][2] = fmaf(a.w, bb.z, acc[3][2]); acc[3][3] = fmaf(a.w, bb.w, acc[3][3]);
    }
  }

#pragma unroll
  for (int i = 0; i < 4; i++) {
    int s = s0 + (ty << 2) + i;
    float rowsum = 0.f;
#pragma unroll
    for (int j = 0; j < 4; j++) {
      int t = t0 + (tx << 2) + j;
      uint32_t q = ((uint32_t)b << 16) | ((uint32_t)s << 8) | (uint32_t)t;
      float bit;
      if (s == t) bit = 1.0f;
      else bit = hard_bit_fast(acc[i][j], q, sW1, sb1, sW2, sb2, sW3, sb3);
      g_adj[q] = bit;
      rowsum += bit;
    }
    // reduce over the 16 tx lanes (half-warp), then one atomic per row chunk
#pragma unroll
    for (int o = 8; o; o >>= 1)
      rowsum += __shfl_down_sync(0xFFFFFFFFu, rowsum, o, 16);
    if (tx == 0) atomicAdd(&g_deg[b * NS + s], rowsum);
  }
}

// ---------------------------------------------------------------------------
// TF32 tensor-core GEMM core: 128x128 block, 8 warps x (64x32 warp tile),
// k-tile 8 double-buffered.  A smem [128][12] (pad), B smem [8][132] (pad).
// (Exact R11 layout — scalar fragment LDS, conflict-free stores.)
// ---------------------------------------------------------------------------
#define APAD 12
#define BPAD 132

// Kernel 3: Y[bc] = (1/deg) * (adj[b] @ F[bc])   — A (adj) is exact in tf32
__global__ void __launch_bounds__(256) prop_kernel(const float* __restrict__ features) {
  __shared__ uint32_t As[2][128][APAD];
  __shared__ uint32_t Bs[2][8][BPAD];

  const int tid = threadIdx.x;
  const int bc = blockIdx.z;
  const int b  = bc >> 2;
  const int s0 = blockIdx.y * 128;
  const int d0 = blockIdx.x * 128;

  const float* A  = g_adj + (size_t)b * NS * NS;
  const float* Bm = features + (size_t)bc * NS * NDIN;

  const int ar = tid >> 1, ac = (tid & 1) << 2;
  const int brow = tid >> 5, bcol = (tid & 31) << 2;

  const int wid = tid >> 5, lane = tid & 31;
  const int wm = (wid >> 2) * 64, wn = (wid & 3) * 32;
  const int gid = lane >> 2, t4 = lane & 3;

  float c[4][4][4];
#pragma unroll
  for (int i = 0; i < 4; i++)
#pragma unroll
    for (int j = 0; j < 4; j++)
#pragma unroll
      for (int r = 0; r < 4; r++) c[i][j][r] = 0.f;

  // preload tile 0
  {
    float4 av = *reinterpret_cast<const float4*>(A  + (s0 + ar) * NS + ac);
    float4 bv = *reinterpret_cast<const float4*>(Bm + brow * NDIN + d0 + bcol);
    As[0][ar][ac + 0] = to_tf32(av.x); As[0][ar][ac + 1] = to_tf32(av.y);
    As[0][ar][ac + 2] = to_tf32(av.z); As[0][ar][ac + 3] = to_tf32(av.w);
    Bs[0][brow][bcol + 0] = to_tf32(bv.x); Bs[0][brow][bcol + 1] = to_tf32(bv.y);
    Bs[0][brow][bcol + 2] = to_tf32(bv.z); Bs[0][brow][bcol + 3] = to_tf32(bv.w);
  }
  __syncthreads();

  const int NK = NS / 8;
  for (int kt = 0; kt < NK; kt++) {
    const int cur = kt & 1;
    float4 av, bv;
    if (kt + 1 < NK) {
      int k0 = (kt + 1) * 8;
      av = *reinterpret_cast<const float4*>(A  + (s0 + ar) * NS + k0 + ac);
      bv = *reinterpret_cast<const float4*>(Bm + (k0 + brow) * NDIN + d0 + bcol);
    }
    uint32_t afr[4][4], bfr[4][2];
#pragma unroll
    for (int i = 0; i < 4; i++) {
      int row = wm + i * 16 + gid;
      afr[i][0] = As[cur][row][t4];
      afr[i][1] = As[cur][row + 8][t4];
      afr[i][2] = As[cur][row][t4 + 4];
      afr[i][3] = As[cur][row + 8][t4 + 4];
    }
#pragma unroll
    for (int j = 0; j < 4; j++) {
      int col = wn + j * 8 + gid;
      bfr[j][0] = Bs[cur][t4][col];
      bfr[j][1] = Bs[cur][t4 + 4][col];
    }
#pragma unroll
    for (int i = 0; i < 4; i++)
#pragma unroll
      for (int j = 0; j < 4; j++)
        mma_tf32(c[i][j], afr[i][0], afr[i][1], afr[i][2], afr[i][3],
                 bfr[j][0], bfr[j][1]);
    if (kt + 1 < NK) {
      const int nxt = 1 - cur;
      As[nxt][ar][ac + 0] = to_tf32(av.x); As[nxt][ar][ac + 1] = to_tf32(av.y);
      As[nxt][ar][ac + 2] = to_tf32(av.z); As[nxt][ar][ac + 3] = to_tf32(av.w);
      Bs[nxt][brow][bcol + 0] = to_tf32(bv.x); Bs[nxt][brow][bcol + 1] = to_tf32(bv.y);
      Bs[nxt][brow][bcol + 2] = to_tf32(bv.z); Bs[nxt][brow][bcol + 3] = to_tf32(bv.w);
      __syncthreads();
    }
  }

#pragma unroll
  for (int i = 0; i < 4; i++) {
    int r0 = s0 + wm + i * 16 + gid;
    int r1 = r0 + 8;
    float sc0 = 1.0f / g_deg[b * NS + r0];
    float sc1 = 1.0f / g_deg[b * NS + r1];
#pragma unroll
    for (int j = 0; j < 4; j++) {
      int col = d0 + wn + j * 8 + 2 * t4;
      float* p0 = &g_Y[((size_t)bc * NS + r0) * NDIN + col];
      float* p1 = &g_Y[((size_t)bc * NS + r1) * NDIN + col];
      *reinterpret_cast<float2*>(p0) = make_float2(sc0 * c[i][j][0], sc0 * c[i][j][1]);
      *reinterpret_cast<float2*>(p1) = make_float2(sc1 * c[i][j][2], sc1 * c[i][j][3]);
    }
  }
}

// Kernel 4: out = Y @ Wl + bl   (32768 x 256 x 256, tf32 MMA)
__global__ void __launch_bounds__(256) out_kernel(const float* __restrict__ Wl,
                                                  const float* __restrict__ bl,
                                                  float* __restrict__ out) {
  __shared__ uint32_t As[2][128][APAD];
  __shared__ uint32_t Bs[2][8][BPAD];

  const int tid = threadIdx.x;
  const int m0 = blockIdx.y * 128;
  const int n0 = blockIdx.x * 128;

  const int ar = tid >> 1, ac = (tid & 1) << 2;
  const int brow = tid >> 5, bcol = (tid & 31) << 2;

  const int wid = tid >> 5, lane = tid & 31;
  const int wm = (wid >> 2) * 64, wn = (wid & 3) * 32;
  const int gid = lane >> 2, t4 = lane & 3;

  float c[4][4][4];
#pragma unroll
  for (int i = 0; i < 4; i++)
#pragma unroll
    for (int j = 0; j < 4; j++)
#pragma unroll
      for (int r = 0; r < 4; r++) c[i][j][r] = 0.f;

  {
    float4 av = *reinterpret_cast<const float4*>(&g_Y[(size_t)(m0 + ar) * NDIN + ac]);
    float4 bv = *reinterpret_cast<const float4*>(Wl + brow * NDOUT + n0 + bcol);
    As[0][ar][ac + 0] = to_tf32(av.x); As[0][ar][ac + 1] = to_tf32(av.y);
    As[0][ar][ac + 2] = to_tf32(av.z); As[0][ar][ac + 3] = to_tf32(av.w);
    Bs[0][brow][bcol + 0] = to_tf32(bv.x); Bs[0][brow][bcol + 1] = to_tf32(bv.y);
    Bs[0][brow][bcol + 2] = to_tf32(bv.z); Bs[0][brow][bcol + 3] = to_tf32(bv.w);
  }
  __syncthreads();

  const int NK = NDIN / 8;
  for (int kt = 0; kt < NK; kt++) {
    const int cur = kt & 1;
    float4 av, bv;
    if (kt + 1 < NK) {
      int k0 = (kt + 1) * 8;
      av = *reinterpret_cast<const float4*>(&g_Y[(size_t)(m0 + ar) * NDIN + k0 + ac]);
      bv = *reinterpret_cast<const float4*>(Wl + (k0 + brow) * NDOUT + n0 + bcol);
    }
    uint32_t afr[4][4], bfr[4][2];
#pragma unroll
    for (int i = 0; i < 4; i++) {
      int row = wm + i * 16 + gid;
      afr[i][0] = As[cur][row][t4];
      afr[i][1] = As[cur][row + 8][t4];
      afr[i][2] = As[cur][row][t4 + 4];
      afr[i][3] = As[cur][row + 8][t4 + 4];
    }
#pragma unroll
    for (int j = 0; j < 4; j++) {
      int col = wn + j * 8 + gid;
      bfr[j][0] = Bs[cur][t4][col];
      bfr[j][1] = Bs[cur][t4 + 4][col];
    }
#pragma unroll
    for (int i = 0; i < 4; i++)
#pragma unroll
      for (int j = 0; j < 4; j++)
        mma_tf32(c[i][j], afr[i][0], afr[i][1], afr[i][2], afr[i][3],
                 bfr[j][0], bfr[j][1]);
    if (kt + 1 < NK) {
      const int nxt = 1 - cur;
      As[nxt][ar][ac + 0] = to_tf32(av.x); As[nxt][ar][ac + 1] = to_tf32(av.y);
      As[nxt][ar][ac + 2] = to_tf32(av.z); As[nxt][ar][ac + 3] = to_tf32(av.w);
      Bs[nxt][brow][bcol + 0] = to_tf32(bv.x); Bs[nxt][brow][bcol + 1] = to_tf32(bv.y);
      Bs[nxt][brow][bcol + 2] = to_tf32(bv.z); Bs[nxt][brow][bcol + 3] = to_tf32(bv.w);
      __syncthreads();
    }
  }

#pragma unroll
  for (int i = 0; i < 4; i++) {
    int r0 = m0 + wm + i * 16 + gid;
    int r1 = r0 + 8;
#pragma unroll
    for (int j = 0; j < 4; j++) {
      int col = n0 + wn + j * 8 + 2 * t4;
      float2 bias = *reinterpret_cast<const float2*>(bl + col);
      float* p0 = &out[(size_t)r0 * NDOUT + col];
      float* p1 = &out[(size_t)r1 * NDOUT + col];
      *reinterpret_cast<float2*>(p0) = make_float2(c[i][j][0] + bias.x, c[i][j][1] + bias.y);
      *reinterpret_cast<float2*>(p1) = make_float2(c[i][j][2] + bias.x, c[i][j][3] + bias.y);
    }
  }
}

// ---------------------------------------------------------------------------
extern "C" void kernel_launch(void* const* d_in, const int* in_sizes, int n_in,
                              void* d_out, int out_size) {
  const float *features = 0, *fm = 0, *W1 = 0, *b1 = 0, *W2 = 0, *b2 = 0,
              *W3 = 0, *b3 = 0, *Wl = 0, *bl = 0;
  int n16 = 0;
  for (int i = 0; i < n_in; i++) {
    const float* p = (const float*)d_in[i];
    switch (in_sizes[i]) {
      case 8388608: features = p; break;
      case 2097152: fm = p; break;
      case 128:     W2 = p; break;
      case 8:       b2 = p; break;
      case 2:       b3 = p; break;
      case 65536:   Wl = p; break;
      case 256:     bl = p; break;
      case 16:
        if (n16 == 0) W1 = p; else if (n16 == 1) b1 = p; else W3 = p;
        n16++; break;
      default: break;
    }
  }
  float* out = (float*)d_out;

  build_tab_kernel<<<(TAB_N + 256) / 256, 256>>>(W1, b1, W2, b2, W3, b3);
  adj_kernel<<<dim3(4, 4, 32), 256>>>(fm, W1, b1, W2, b2, W3, b3);
  prop_kernel<<<dim3(2, 2, 128), 256>>>(features);
  out_kernel<<<dim3(2, 256, 1), 256>>>(Wl, bl, out);
}

// round 16
// speedup vs baseline: 1.5740x; 1.0542x over previous
#include <cuda_runtime.h>
#include <stdint.h>

#define NB 32
#define NC 4
#define NS 256
#define NL 256
#define NDIN 256
#define NDOUT 256

#define TAB_N 16384
#define TAB_SCALE 64.0f
#define TAB_H (1.0f / 64.0f)

__device__ float g_adj[NB * NS * NS];
__device__ float g_invdeg[NB * NS];
__device__ float g_Y[(size_t)NB * NC * NS * NDIN];
__device__ float2 g_tab[TAB_N + 1];

// ---------------------------------------------------------------------------
// Threefry-2x32, key=(0,42); partitionable XOR-fold bits (JAX >= 0.4.36)
// ---------------------------------------------------------------------------
__device__ __forceinline__ void threefry(uint32_t x0, uint32_t x1,
                                         uint32_t& o0, uint32_t& o1) {
  const uint32_t ks0 = 0u, ks1 = 42u, ks2 = 0u ^ 42u ^ 0x1BD11BDAu;
  x0 += ks0; x1 += ks1;
#define TF_R(r) { x0 += x1; x1 = __funnelshift_l(x1, x1, (r)); x1 ^= x0; }
  TF_R(13) TF_R(15) TF_R(26) TF_R(6)
  x0 += ks1; x1 += ks2 + 1u;
  TF_R(17) TF_R(29) TF_R(16) TF_R(24)
  x0 += ks2; x1 += ks0 + 2u;
  TF_R(13) TF_R(15) TF_R(26) TF_R(6)
  x0 += ks0; x1 += ks1 + 3u;
  TF_R(17) TF_R(29) TF_R(16) TF_R(24)
  x0 += ks1; x1 += ks2 + 4u;
  TF_R(13) TF_R(15) TF_R(26) TF_R(6)
  x0 += ks2; x1 += ks0 + 5u;
#undef TF_R
  o0 = x0; o1 = x1;
}

__device__ __forceinline__ uint32_t jax_bits(uint32_t p) {
  uint32_t o0, o1;
  threefry(0u, p, o0, o1);
  return o0 ^ o1;
}

__device__ __forceinline__ float bits_to_gumbel(uint32_t bits) {
  float f = __uint_as_float((bits >> 9) | 0x3F800000u) - 1.0f;
  float u = fmaxf(1e-10f, f + 1e-10f);
  return -logf(-logf(u));
}

__device__ __forceinline__ float gelu_exact(float x) {
  return 0.5f * x * (1.0f + erff(x * 0.70710678118654752440f));
}

// TF32 helpers
__device__ __forceinline__ uint32_t to_tf32(float x) {
  uint32_t r;
  asm("cvt.rna.tf32.f32 %0, %1;" : "=r"(r) : "f"(x));
  return r;
}
__device__ __forceinline__ void mma_tf32(float c[4],
    uint32_t a0, uint32_t a1, uint32_t a2, uint32_t a3,
    uint32_t b0, uint32_t b1) {
  asm volatile(
    "mma.sync.aligned.m16n8k8.row.col.f32.tf32.tf32.f32 "
    "{%0,%1,%2,%3}, {%4,%5,%6,%7}, {%8,%9}, {%0,%1,%2,%3};"
    : "+f"(c[0]), "+f"(c[1]), "+f"(c[2]), "+f"(c[3])
    : "r"(a0), "r"(a1), "r"(a2), "r"(a3), "r"(b0), "r"(b1));
}

// cp.async helpers (Ampere+, fine on sm_100 base target)
__device__ __forceinline__ uint32_t smem_u32(const void* p) {
  uint32_t a;
  asm("{ .reg .u64 t; cvta.to.shared.u64 t, %1; cvt.u32.u64 %0, t; }" : "=r"(a) : "l"(p));
  return a;
}
#define CP_ASYNC16(dst_u32, src_ptr) \
  asm volatile("cp.async.cg.shared.global [%0], [%1], 16;" :: "r"(dst_u32), "l"(src_ptr) : "memory")
#define CP_COMMIT()   asm volatile("cp.async.commit_group;" ::: "memory")
#define CP_WAIT0()    asm volatile("cp.async.wait_group 0;" ::: "memory")

// ---------------------------------------------------------------------------
// Exact MLP margin (fallback for |c| >= 128 — essentially never taken)
// ---------------------------------------------------------------------------
__device__ __forceinline__ void mlp_z(float c,
    const float* __restrict__ W1, const float* __restrict__ b1,
    const float* __restrict__ W2, const float* __restrict__ b2,
    const float* __restrict__ W3, const float* __restrict__ b3,
    float& z0, float& z1)
{
  float h1[16];
#pragma unroll
  for (int j = 0; j < 16; j++) h1[j] = gelu_exact(fmaf(c, W1[j], b1[j]));
  float h2[8];
#pragma unroll
  for (int k = 0; k < 8; k++) {
    float a = b2[k];
#pragma unroll
    for (int j = 0; j < 16; j++) a = fmaf(h1[j], W2[j * 8 + k], a);
    h2[k] = gelu_exact(a);
  }
  z0 = b3[0]; z1 = b3[1];
#pragma unroll
  for (int k = 0; k < 8; k++) {
    z0 = fmaf(h2[k], W3[2 * k + 0], z0);
    z1 = fmaf(h2[k], W3[2 * k + 1], z1);
  }
}

// ---------------------------------------------------------------------------
// Kernel 0: Hermite table of f(c)=z0-z1, f'(c)
// ---------------------------------------------------------------------------
__global__ void __launch_bounds__(256) build_tab_kernel(
    const float* __restrict__ W1, const float* __restrict__ b1,
    const float* __restrict__ W2, const float* __restrict__ b2,
    const float* __restrict__ W3, const float* __restrict__ b3)
{
  int i = blockIdx.x * blockDim.x + threadIdx.x;
  if (i > TAB_N) return;
  float c = (float)(i - TAB_N / 2) * TAB_H;

  float h1[16], dh1[16];
#pragma unroll
  for (int j = 0; j < 16; j++) {
    float a = fmaf(c, W1[j], b1[j]);
    float e = erff(a * 0.70710678118654752440f);
    float phi = 0.3989422804014327f * expf(-0.5f * a * a);
    h1[j]  = 0.5f * a * (1.0f + e);
    dh1[j] = (0.5f * (1.0f + e) + a * phi) * W1[j];
  }
  float h2[8], dh2[8];
#pragma unroll
  for (int k = 0; k < 8; k++) {
    float a = b2[k], da = 0.f;
#pragma unroll
    for (int j = 0; j < 16; j++) {
      a  = fmaf(h1[j],  W2[j * 8 + k], a);
      da = fmaf(dh1[j], W2[j * 8 + k], da);
    }
    float e = erff(a * 0.70710678118654752440f);
    float phi = 0.3989422804014327f * expf(-0.5f * a * a);
    h2[k]  = 0.5f * a * (1.0f + e);
    dh2[k] = (0.5f * (1.0f + e) + a * phi) * da;
  }
  float z0 = b3[0], z1 = b3[1], d0 = 0.f, d1 = 0.f;
#pragma unroll
  for (int k = 0; k < 8; k++) {
    z0 = fmaf(h2[k],  W3[2 * k + 0], z0);
    z1 = fmaf(h2[k],  W3[2 * k + 1], z1);
    d0 = fmaf(dh2[k], W3[2 * k + 0], d0);
    d1 = fmaf(dh2[k], W3[2 * k + 1], d1);
  }
  g_tab[i] = make_float2(z0 - z1, d0 - d1);
}

// ---------------------------------------------------------------------------
// Fast adjacency bit: spline margin + gumbel saturation skip
// ---------------------------------------------------------------------------
__device__ __forceinline__ float hard_bit_fast(float c, uint32_t q,
    const float* __restrict__ sW1, const float* __restrict__ sb1,
    const float* __restrict__ sW2, const float* __restrict__ sb2,
    const float* __restrict__ sW3, const float* __restrict__ sb3)
{
  float d;
  float u = fmaf(c, TAB_SCALE, (float)(TAB_N / 2));
  float fl = floorf(u);
  int i = (int)fl;
  if (i >= 0 && i < TAB_N) {
    float t = u - fl;
    float2 p0 = g_tab[i];
    float2 p1 = g_tab[i + 1];
    float m0 = p0.y * TAB_H, m1 = p1.y * TAB_H;
    float t2 = t * t, t3 = t2 * t;
    d = p0.x * (2.f * t3 - 3.f * t2 + 1.f) + m0 * (t3 - 2.f * t2 + t)
      + p1.x * (3.f * t2 - 2.f * t3)       + m1 * (t3 - t2);
  } else {
    float z0, z1;
    mlp_z(c, sW1, sb1, sW2, sb2, sW3, sb3, z0, z1);
    d = z0 - z1;
  }
  if (d >  19.5f) return 1.0f;
  if (d < -19.5f) return 0.0f;
  float g0 = bits_to_gumbel(jax_bits(2u * q));
  float g1 = bits_to_gumbel(jax_bits(2u * q + 1u));
  return (d + g0 >= g1) ? 1.0f : 0.0f;
}

// ---------------------------------------------------------------------------
// Kernel 1: adjacency bits (R11, unchanged)
// ---------------------------------------------------------------------------
__global__ void __launch_bounds__(256) adj_kernel(
    const float* __restrict__ fm,
    const float* __restrict__ W1, const float* __restrict__ b1,
    const float* __restrict__ W2, const float* __restrict__ b2,
    const float* __restrict__ W3, const float* __restrict__ b3)
{
  __shared__ float As[16][64];
  __shared__ float Bs[16][64];
  __shared__ float sW1[16], sb1[16], sW2[128], sb2[8], sW3[16], sb3[2];

  const int tid = threadIdx.x;
  const int b  = blockIdx.z;
  const int s0 = blockIdx.y * 64;
  const int t0 = blockIdx.x * 64;

  if (tid < 16)        sW1[tid]       = W1[tid];
  else if (tid < 32)   sb1[tid - 16]  = b1[tid - 16];
  else if (tid < 160)  sW2[tid - 32]  = W2[tid - 32];
  else if (tid < 168)  sb2[tid - 160] = b2[tid - 160];
  else if (tid < 184)  sW3[tid - 168] = W3[tid - 168];
  else if (tid < 186)  sb3[tid - 184] = b3[tid - 184];

  const float* A = fm + (size_t)b * NS * NL;
  const int lr = tid >> 2;
  const int lc = (tid & 3) << 2;
  const int ty = tid >> 4;
  const int tx = tid & 15;

  float acc[4][4];
#pragma unroll
  for (int i = 0; i < 4; i++)
#pragma unroll
    for (int j = 0; j < 4; j++) acc[i][j] = 0.f;

  for (int k0 = 0; k0 < NL; k0 += 16) {
    float4 av = *reinterpret_cast<const float4*>(A + (s0 + lr) * NL + k0 + lc);
    float4 bv = *reinterpret_cast<const float4*>(A + (t0 + lr) * NL + k0 + lc);
    __syncthreads();
    As[lc + 0][lr] = av.x; As[lc + 1][lr] = av.y; As[lc + 2][lr] = av.z; As[lc + 3][lr] = av.w;
    Bs[lc + 0][lr] = bv.x; Bs[lc + 1][lr] = bv.y; Bs[lc + 2][lr] = bv.z; Bs[lc + 3][lr] = bv.w;
    __syncthreads();
#pragma unroll
    for (int k = 0; k < 16; k++) {
      float4 a  = *reinterpret_cast<const float4*>(&As[k][ty << 2]);
      float4 bb = *reinterpret_cast<const float4*>(&Bs[k][tx << 2]);
      acc[0][0] = fmaf(a.x, bb.x, acc[0][0]); acc[0][1] = fmaf(a.x, bb.y, acc[0][1]);
      acc[0][2] = fmaf(a.x, bb.z, acc[0][2]); acc[0][3] = fmaf(a.x, bb.w, acc[0][3]);
      acc[1][0] = fmaf(a.y, bb.x, acc[1][0]); acc[1][1] = fmaf(a.y, bb.y, acc[1][1]);
      acc[1][2] = fmaf(a.y, bb.z, acc[1][2]); acc[1][3] = fmaf(a.y, bb.w, acc[1][3]);
      acc[2][0] = fmaf(a.z, bb.x, acc[2][0]); acc[2][1] = fmaf(a.z, bb.y, acc[2][1]);
      acc[2][2] = fmaf(a.z, bb.z, acc[2][2]); acc[2][3] = fmaf(a.z, bb.w, acc[2][3]);
      acc[3][0] = fmaf(a.w, bb.x, acc[3][0]); acc[3][1] = fmaf(a.w, bb.y, acc[3][1]);
      acc[3][2] = fmaf(a.w, bb.z, acc[3][2]); acc[3][3] = fmaf(a.w, bb.w, acc[3][3]);
    }
  }

#pragma unroll
  for (int i = 0; i < 4; i++) {
    int s = s0 + (ty << 2) + i;
#pragma unroll
    for (int j = 0; j < 4; j++) {
      int t = t0 + (tx << 2) + j;
      uint32_t q = ((uint32_t)b << 16) | ((uint32_t)s << 8) | (uint32_t)t;
      float bit;
      if (s == t) bit = 1.0f;
      else bit = hard_bit_fast(acc[i][j], q, sW1, sb1, sW2, sb2, sW3, sb3);
      g_adj[q] = bit;
    }
  }
}

// ---------------------------------------------------------------------------
// Kernel 2: inverse degree per row (R11, unchanged)
// ---------------------------------------------------------------------------
__global__ void __launch_bounds__(256) invdeg_kernel() {
  int warp = (blockIdx.x * blockDim.x + threadIdx.x) >> 5;
  int lane = threadIdx.x & 31;
  if (warp >= NB * NS) return;
  const float* row = g_adj + (size_t)warp * NS;
  float s = 0.f;
#pragma unroll
  for (int t = lane; t < NS; t += 32) s += row[t];
#pragma unroll
  for (int o = 16; o; o >>= 1) s += __shfl_xor_sync(0xFFFFFFFFu, s, o);
  if (lane == 0) g_invdeg[warp] = 1.0f / s;
}

// ---------------------------------------------------------------------------
// TF32 mma.sync GEMM (R11 layout) with cp.async staging:
// raw f32 in smem, cvt.rna at fragment load.  128x128 block, 8 warps x 64x32,
// k-tile 8 double-buffered, copies overlapped with MMA via cp.async groups.
// ---------------------------------------------------------------------------
#define APAD 12
#define BPAD 132

// Kernel 3: Y[bc] = invdeg * (adj[b] @ F[bc])
__global__ void __launch_bounds__(256) prop_kernel(const float* __restrict__ features) {
  __shared__ float As[2][128][APAD];
  __shared__ float Bs[2][8][BPAD];

  const int tid = threadIdx.x;
  const int bc = blockIdx.z;
  const int b  = bc >> 2;
  const int s0 = blockIdx.y * 128;
  const int d0 = blockIdx.x * 128;

  const float* A  = g_adj + (size_t)b * NS * NS;
  const float* Bm = features + (size_t)bc * NS * NDIN;

  const int ar = tid >> 1, ac = (tid & 1) << 2;
  const int brow = tid >> 5, bcol = (tid & 31) << 2;

  const int wid = tid >> 5, lane = tid & 31;
  const int wm = (wid >> 2) * 64, wn = (wid & 3) * 32;
  const int gid = lane >> 2, t4 = lane & 3;

  const uint32_t sa0 = smem_u32(&As[0][ar][ac]);
  const uint32_t sa1 = smem_u32(&As[1][ar][ac]);
  const uint32_t sb0 = smem_u32(&Bs[0][brow][bcol]);
  const uint32_t sb1 = smem_u32(&Bs[1][brow][bcol]);

  float c[4][4][4];
#pragma unroll
  for (int i = 0; i < 4; i++)
#pragma unroll
    for (int j = 0; j < 4; j++)
#pragma unroll
      for (int r = 0; r < 4; r++) c[i][j][r] = 0.f;

  // preload tile 0
  CP_ASYNC16(sa0, A  + (size_t)(s0 + ar) * NS + ac);
  CP_ASYNC16(sb0, Bm + (size_t)brow * NDIN + d0 + bcol);
  CP_COMMIT();
  CP_WAIT0();
  __syncthreads();

  const int NK = NS / 8;
  for (int kt = 0; kt < NK; kt++) {
    const int cur = kt & 1;
    if (kt + 1 < NK) {
      int k0 = (kt + 1) * 8;
      CP_ASYNC16(cur ? sa0 : sa1, A  + (size_t)(s0 + ar) * NS + k0 + ac);
      CP_ASYNC16(cur ? sb0 : sb1, Bm + (size_t)(k0 + brow) * NDIN + d0 + bcol);
      CP_COMMIT();
    }
    uint32_t afr[4][4], bfr[4][2];
#pragma unroll
    for (int i = 0; i < 4; i++) {
      int row = wm + i * 16 + gid;
      afr[i][0] = to_tf32(As[cur][row][t4]);
      afr[i][1] = to_tf32(As[cur][row + 8][t4]);
      afr[i][2] = to_tf32(As[cur][row][t4 + 4]);
      afr[i][3] = to_tf32(As[cur][row + 8][t4 + 4]);
    }
#pragma unroll
    for (int j = 0; j < 4; j++) {
      int col = wn + j * 8 + gid;
      bfr[j][0] = to_tf32(Bs[cur][t4][col]);
      bfr[j][1] = to_tf32(Bs[cur][t4 + 4][col]);
    }
#pragma unroll
    for (int i = 0; i < 4; i++)
#pragma unroll
      for (int j = 0; j < 4; j++)
        mma_tf32(c[i][j], afr[i][0], afr[i][1], afr[i][2], afr[i][3],
                 bfr[j][0], bfr[j][1]);
    if (kt + 1 < NK) {
      CP_WAIT0();
      __syncthreads();
    }
  }

#pragma unroll
  for (int i = 0; i < 4; i++) {
    int r0 = s0 + wm + i * 16 + gid;
    int r1 = r0 + 8;
    float sc0 = g_invdeg[b * NS + r0];
    float sc1 = g_invdeg[b * NS + r1];
#pragma unroll
    for (int j = 0; j < 4; j++) {
      int col = d0 + wn + j * 8 + 2 * t4;
      float* p0 = &g_Y[((size_t)bc * NS + r0) * NDIN + col];
      float* p1 = &g_Y[((size_t)bc * NS + r1) * NDIN + col];
      *reinterpret_cast<float2*>(p0) = make_float2(sc0 * c[i][j][0], sc0 * c[i][j][1]);
      *reinterpret_cast<float2*>(p1) = make_float2(sc1 * c[i][j][2], sc1 * c[i][j][3]);
    }
  }
}

// Kernel 4: out = Y @ Wl + bl   (32768 x 256 x 256)
__global__ void __launch_bounds__(256) out_kernel(const float* __restrict__ Wl,
                                                  const float* __restrict__ bl,
                                                  float* __restrict__ out) {
  __shared__ float As[2][128][APAD];
  __shared__ float Bs[2][8][BPAD];

  const int tid = threadIdx.x;
  const int m0 = blockIdx.y * 128;
  const int n0 = blockIdx.x * 128;

  const int ar = tid >> 1, ac = (tid & 1) << 2;
  const int brow = tid >> 5, bcol = (tid & 31) << 2;

  const int wid = tid >> 5, lane = tid & 31;
  const int wm = (wid >> 2) * 64, wn = (wid & 3) * 32;
  const int gid = lane >> 2, t4 = lane & 3;

  const uint32_t sa0 = smem_u32(&As[0][ar][ac]);
  const uint32_t sa1 = smem_u32(&As[1][ar][ac]);
  const uint32_t sb0 = smem_u32(&Bs[0][brow][bcol]);
  const uint32_t sb1 = smem_u32(&Bs[1][brow][bcol]);

  float c[4][4][4];
#pragma unroll
  for (int i = 0; i < 4; i++)
#pragma unroll
    for (int j = 0; j < 4; j++)
#pragma unroll
      for (int r = 0; r < 4; r++) c[i][j][r] = 0.f;

  CP_ASYNC16(sa0, g_Y + (size_t)(m0 + ar) * NDIN + ac);
  CP_ASYNC16(sb0, Wl + (size_t)brow * NDOUT + n0 + bcol);
  CP_COMMIT();
  CP_WAIT0();
  __syncthreads();

  const int NK = NDIN / 8;
  for (int kt = 0; kt < NK; kt++) {
    const int cur = kt & 1;
    if (kt + 1 < NK) {
      int k0 = (kt + 1) * 8;
      CP_ASYNC16(cur ? sa0 : sa1, g_Y + (size_t)(m0 + ar) * NDIN + k0 + ac);
      CP_ASYNC16(cur ? sb0 : sb1, Wl + (size_t)(k0 + brow) * NDOUT + n0 + bcol);
      CP_COMMIT();
    }
    uint32_t afr[4][4], bfr[4][2];
#pragma unroll
    for (int i = 0; i < 4; i++) {
      int row = wm + i * 16 + gid;
      afr[i][0] = to_tf32(As[cur][row][t4]);
      afr[i][1] = to_tf32(As[cur][row + 8][t4]);
      afr[i][2] = to_tf32(As[cur][row][t4 + 4]);
      afr[i][3] = to_tf32(As[cur][row + 8][t4 + 4]);
    }
#pragma unroll
    for (int j = 0; j < 4; j++) {
      int col = wn + j * 8 + gid;
      bfr[j][0] = to_tf32(Bs[cur][t4][col]);
      bfr[j][1] = to_tf32(Bs[cur][t4 + 4][col]);
    }
#pragma unroll
    for (int i = 0; i < 4; i++)
#pragma unroll
      for (int j = 0; j < 4; j++)
        mma_tf32(c[i][j], afr[i][0], afr[i][1], afr[i][2], afr[i][3],
                 bfr[j][0], bfr[j][1]);
    if (kt + 1 < NK) {
      CP_WAIT0();
      __syncthreads();
    }
  }

#pragma unroll
  for (int i = 0; i < 4; i++) {
    int r0 = m0 + wm + i * 16 + gid;
    int r1 = r0 + 8;
#pragma unroll
    for (int j = 0; j < 4; j++) {
      int col = n0 + wn + j * 8 + 2 * t4;
      float2 bias = *reinterpret_cast<const float2*>(bl + col);
      float* p0 = &out[(size_t)r0 * NDOUT + col];
      float* p1 = &out[(size_t)r1 * NDOUT + col];
      *reinterpret_cast<float2*>(p0) = make_float2(c[i][j][0] + bias.x, c[i][j][1] + bias.y);
      *reinterpret_cast<float2*>(p1) = make_float2(c[i][j][2] + bias.x, c[i][j][3] + bias.y);
    }
  }
}

// ---------------------------------------------------------------------------
extern "C" void kernel_launch(void* const* d_in, const int* in_sizes, int n_in,
                              void* d_out, int out_size) {
  const float *features = 0, *fm = 0, *W1 = 0, *b1 = 0, *W2 = 0, *b2 = 0,
              *W3 = 0, *b3 = 0, *Wl = 0, *bl = 0;
  int n16 = 0;
  for (int i = 0; i < n_in; i++) {
    const float* p = (const float*)d_in[i];
    switch (in_sizes[i]) {
      case 8388608: features = p; break;
      case 2097152: fm = p; break;
      case 128:     W2 = p; break;
      case 8:       b2 = p; break;
      case 2:       b3 = p; break;
      case 65536:   Wl = p; break;
      case 256:     bl = p; break;
      case 16:
        if (n16 == 0) W1 = p; else if (n16 == 1) b1 = p; else W3 = p;
        n16++; break;
      default: break;
    }
  }
  float* out = (float*)d_out;

  build_tab_kernel<<<(TAB_N + 256) / 256, 256>>>(W1, b1, W2, b2, W3, b3);
  adj_kernel<<<dim3(4, 4, 32), 256>>>(fm, W1, b1, W2, b2, W3, b3);
  invdeg_kernel<<<(NB * NS) / 8, 256>>>();
  prop_kernel<<<dim3(2, 2, 128), 256>>>(features);
  out_kernel<<<dim3(2, 256, 1), 256>>>(Wl, bl, out);
}

// round 17
// speedup vs baseline: 1.5921x; 1.0115x over previous
#include <cuda_runtime.h>
#include <stdint.h>

#define NB 32
#define NC 4
#define NS 256
#define NL 256
#define NDIN 256
#define NDOUT 256

#define TAB_N 16384
#define TAB_SCALE 64.0f
#define TAB_H (1.0f / 64.0f)

__device__ float g_adj[NB * NS * NS];
__device__ float g_Y[(size_t)NB * NC * NS * NDIN];
__device__ float2 g_tab[TAB_N + 1];

// ---------------------------------------------------------------------------
// Threefry-2x32, key=(0,42); partitionable XOR-fold bits (JAX >= 0.4.36)
// ---------------------------------------------------------------------------
__device__ __forceinline__ void threefry(uint32_t x0, uint32_t x1,
                                         uint32_t& o0, uint32_t& o1) {
  const uint32_t ks0 = 0u, ks1 = 42u, ks2 = 0u ^ 42u ^ 0x1BD11BDAu;
  x0 += ks0; x1 += ks1;
#define TF_R(r) { x0 += x1; x1 = __funnelshift_l(x1, x1, (r)); x1 ^= x0; }
  TF_R(13) TF_R(15) TF_R(26) TF_R(6)
  x0 += ks1; x1 += ks2 + 1u;
  TF_R(17) TF_R(29) TF_R(16) TF_R(24)
  x0 += ks2; x1 += ks0 + 2u;
  TF_R(13) TF_R(15) TF_R(26) TF_R(6)
  x0 += ks0; x1 += ks1 + 3u;
  TF_R(17) TF_R(29) TF_R(16) TF_R(24)
  x0 += ks1; x1 += ks2 + 4u;
  TF_R(13) TF_R(15) TF_R(26) TF_R(6)
  x0 += ks2; x1 += ks0 + 5u;
#undef TF_R
  o0 = x0; o1 = x1;
}

__device__ __forceinline__ uint32_t jax_bits(uint32_t p) {
  uint32_t o0, o1;
  threefry(0u, p, o0, o1);
  return o0 ^ o1;
}

__device__ __forceinline__ float bits_to_gumbel(uint32_t bits) {
  float f = __uint_as_float((bits >> 9) | 0x3F800000u) - 1.0f;
  float u = fmaxf(1e-10f, f + 1e-10f);
  return -logf(-logf(u));
}

__device__ __forceinline__ float gelu_exact(float x) {
  return 0.5f * x * (1.0f + erff(x * 0.70710678118654752440f));
}

// TF32 helpers
__device__ __forceinline__ uint32_t to_tf32(float x) {
  uint32_t r;
  asm("cvt.rna.tf32.f32 %0, %1;" : "=r"(r) : "f"(x));
  return r;
}
__device__ __forceinline__ void mma_tf32(float c[4],
    uint32_t a0, uint32_t a1, uint32_t a2, uint32_t a3,
    uint32_t b0, uint32_t b1) {
  asm volatile(
    "mma.sync.aligned.m16n8k8.row.col.f32.tf32.tf32.f32 "
    "{%0,%1,%2,%3}, {%4,%5,%6,%7}, {%8,%9}, {%0,%1,%2,%3};"
    : "+f"(c[0]), "+f"(c[1]), "+f"(c[2]), "+f"(c[3])
    : "r"(a0), "r"(a1), "r"(a2), "r"(a3), "r"(b0), "r"(b1));
}

// cp.async helpers
__device__ __forceinline__ uint32_t smem_u32(const void* p) {
  uint32_t a;
  asm("{ .reg .u64 t; cvta.to.shared.u64 t, %1; cvt.u32.u64 %0, t; }" : "=r"(a) : "l"(p));
  return a;
}
#define CP_ASYNC16(dst_u32, src_ptr) \
  asm volatile("cp.async.cg.shared.global [%0], [%1], 16;" :: "r"(dst_u32), "l"(src_ptr) : "memory")
#define CP_COMMIT()   asm volatile("cp.async.commit_group;" ::: "memory")
#define CP_WAIT0()    asm volatile("cp.async.wait_group 0;" ::: "memory")

// ---------------------------------------------------------------------------
// Exact MLP margin (fallback for |c| >= 128 — essentially never taken)
// ---------------------------------------------------------------------------
__device__ __forceinline__ void mlp_z(float c,
    const float* __restrict__ W1, const float* __restrict__ b1,
    const float* __restrict__ W2, const float* __restrict__ b2,
    const float* __restrict__ W3, const float* __restrict__ b3,
    float& z0, float& z1)
{
  float h1[16];
#pragma unroll
  for (int j = 0; j < 16; j++) h1[j] = gelu_exact(fmaf(c, W1[j], b1[j]));
  float h2[8];
#pragma unroll
  for (int k = 0; k < 8; k++) {
    float a = b2[k];
#pragma unroll
    for (int j = 0; j < 16; j++) a = fmaf(h1[j], W2[j * 8 + k], a);
    h2[k] = gelu_exact(a);
  }
  z0 = b3[0]; z1 = b3[1];
#pragma unroll
  for (int k = 0; k < 8; k++) {
    z0 = fmaf(h2[k], W3[2 * k + 0], z0);
    z1 = fmaf(h2[k], W3[2 * k + 1], z1);
  }
}

// ---------------------------------------------------------------------------
// Kernel 0: Hermite table of f(c)=z0-z1, f'(c)
// ---------------------------------------------------------------------------
__global__ void __launch_bounds__(256) build_tab_kernel(
    const float* __restrict__ W1, const float* __restrict__ b1,
    const float* __restrict__ W2, const float* __restrict__ b2,
    const float* __restrict__ W3, const float* __restrict__ b3)
{
  int i = blockIdx.x * blockDim.x + threadIdx.x;
  if (i > TAB_N) return;
  float c = (float)(i - TAB_N / 2) * TAB_H;

  float h1[16], dh1[16];
#pragma unroll
  for (int j = 0; j < 16; j++) {
    float a = fmaf(c, W1[j], b1[j]);
    float e = erff(a * 0.70710678118654752440f);
    float phi = 0.3989422804014327f * expf(-0.5f * a * a);
    h1[j]  = 0.5f * a * (1.0f + e);
    dh1[j] = (0.5f * (1.0f + e) + a * phi) * W1[j];
  }
  float h2[8], dh2[8];
#pragma unroll
  for (int k = 0; k < 8; k++) {
    float a = b2[k], da = 0.f;
#pragma unroll
    for (int j = 0; j < 16; j++) {
      a  = fmaf(h1[j],  W2[j * 8 + k], a);
      da = fmaf(dh1[j], W2[j * 8 + k], da);
    }
    float e = erff(a * 0.70710678118654752440f);
    float phi = 0.3989422804014327f * expf(-0.5f * a * a);
    h2[k]  = 0.5f * a * (1.0f + e);
    dh2[k] = (0.5f * (1.0f + e) + a * phi) * da;
  }
  float z0 = b3[0], z1 = b3[1], d0 = 0.f, d1 = 0.f;
#pragma unroll
  for (int k = 0; k < 8; k++) {
    z0 = fmaf(h2[k],  W3[2 * k + 0], z0);
    z1 = fmaf(h2[k],  W3[2 * k + 1], z1);
    d0 = fmaf(dh2[k], W3[2 * k + 0], d0);
    d1 = fmaf(dh2[k], W3[2 * k + 1], d1);
  }
  g_tab[i] = make_float2(z0 - z1, d0 - d1);
}

// ---------------------------------------------------------------------------
// Fast adjacency bit: spline margin + gumbel saturation skip
// ---------------------------------------------------------------------------
__device__ __forceinline__ float hard_bit_fast(float c, uint32_t q,
    const float* __restrict__ sW1, const float* __restrict__ sb1,
    const float* __restrict__ sW2, const float* __restrict__ sb2,
    const float* __restrict__ sW3, const float* __restrict__ sb3)
{
  float d;
  float u = fmaf(c, TAB_SCALE, (float)(TAB_N / 2));
  float fl = floorf(u);
  int i = (int)fl;
  if (i >= 0 && i < TAB_N) {
    float t = u - fl;
    float2 p0 = g_tab[i];
    float2 p1 = g_tab[i + 1];
    float m0 = p0.y * TAB_H, m1 = p1.y * TAB_H;
    float t2 = t * t, t3 = t2 * t;
    d = p0.x * (2.f * t3 - 3.f * t2 + 1.f) + m0 * (t3 - 2.f * t2 + t)
      + p1.x * (3.f * t2 - 2.f * t3)       + m1 * (t3 - t2);
  } else {
    float z0, z1;
    mlp_z(c, sW1, sb1, sW2, sb2, sW3, sb3, z0, z1);
    d = z0 - z1;
  }
  if (d >  19.5f) return 1.0f;
  if (d < -19.5f) return 0.0f;
  float g0 = bits_to_gumbel(jax_bits(2u * q));
  float g1 = bits_to_gumbel(jax_bits(2u * q + 1u));
  return (d + g0 >= g1) ? 1.0f : 0.0f;
}

// ---------------------------------------------------------------------------
// Kernel 1: adjacency bits (R11, unchanged)
// ---------------------------------------------------------------------------
__global__ void __launch_bounds__(256) adj_kernel(
    const float* __restrict__ fm,
    const float* __restrict__ W1, const float* __restrict__ b1,
    const float* __restrict__ W2, const float* __restrict__ b2,
    const float* __restrict__ W3, const float* __restrict__ b3)
{
  __shared__ float As[16][64];
  __shared__ float Bs[16][64];
  __shared__ float sW1[16], sb1[16], sW2[128], sb2[8], sW3[16], sb3[2];

  const int tid = threadIdx.x;
  const int b  = blockIdx.z;
  const int s0 = blockIdx.y * 64;
  const int t0 = blockIdx.x * 64;

  if (tid < 16)        sW1[tid]       = W1[tid];
  else if (tid < 32)   sb1[tid - 16]  = b1[tid - 16];
  else if (tid < 160)  sW2[tid - 32]  = W2[tid - 32];
  else if (tid < 168)  sb2[tid - 160] = b2[tid - 160];
  else if (tid < 184)  sW3[tid - 168] = W3[tid - 168];
  else if (tid < 186)  sb3[tid - 184] = b3[tid - 184];

  const float* A = fm + (size_t)b * NS * NL;
  const int lr = tid >> 2;
  const int lc = (tid & 3) << 2;
  const int ty = tid >> 4;
  const int tx = tid & 15;

  float acc[4][4];
#pragma unroll
  for (int i = 0; i < 4; i++)
#pragma unroll
    for (int j = 0; j < 4; j++) acc[i][j] = 0.f;

  for (int k0 = 0; k0 < NL; k0 += 16) {
    float4 av = *reinterpret_cast<const float4*>(A + (s0 + lr) * NL + k0 + lc);
    float4 bv = *reinterpret_cast<const float4*>(A + (t0 + lr) * NL + k0 + lc);
    __syncthreads();
    As[lc + 0][lr] = av.x; As[lc + 1][lr] = av.y; As[lc + 2][lr] = av.z; As[lc + 3][lr] = av.w;
    Bs[lc + 0][lr] = bv.x; Bs[lc + 1][lr] = bv.y; Bs[lc + 2][lr] = bv.z; Bs[lc + 3][lr] = bv.w;
    __syncthreads();
#pragma unroll
    for (int k = 0; k < 16; k++) {
      float4 a  = *reinterpret_cast<const float4*>(&As[k][ty << 2]);
      float4 bb = *reinterpret_cast<const float4*>(&Bs[k][tx << 2]);
      acc[0][0] = fmaf(a.x, bb.x, acc[0][0]); acc[0][1] = fmaf(a.x, bb.y, acc[0][1]);
      acc[0][2] = fmaf(a.x, bb.z, acc[0][2]); acc[0][3] = fmaf(a.x, bb.w, acc[0][3]);
      acc[1][0] = fmaf(a.y, bb.x, acc[1][0]); acc[1][1] = fmaf(a.y, bb.y, acc[1][1]);
      acc[1][2] = fmaf(a.y, bb.z, acc[1][2]); acc[1][3] = fmaf(a.y, bb.w, acc[1][3]);
      acc[2][0] = fmaf(a.z, bb.x, acc[2][0]); acc[2][1] = fmaf(a.z, bb.y, acc[2][1]);
      acc[2][2] = fmaf(a.z, bb.z, acc[2][2]); acc[2][3] = fmaf(a.z, bb.w, acc[2][3]);
      acc[3][0] = fmaf(a.w, bb.x, acc[3][0]); acc[3][1] = fmaf(a.w, bb.y, acc[3][1]);
      acc[3][2] = fmaf(a.w, bb.z, acc[3][2]); acc[3][3] = fmaf(a.w, bb.w, acc[3][3]);
    }
  }

#pragma unroll
  for (int i = 0; i < 4; i++) {
    int s = s0 + (ty << 2) + i;
#pragma unroll
    for (int j = 0; j < 4; j++) {
      int t = t0 + (tx << 2) + j;
      uint32_t q = ((uint32_t)b << 16) | ((uint32_t)s << 8) | (uint32_t)t;
      float bit;
      if (s == t) bit = 1.0f;
      else bit = hard_bit_fast(acc[i][j], q, sW1, sb1, sW2, sb2, sW3, sb3);
      g_adj[q] = bit;
    }
  }
}

// ---------------------------------------------------------------------------
// TF32 mma.sync GEMM (R16 structure).  prop additionally computes the row
// degrees (exact {0,1} sums) from the A values it already streams, so the
// separate invdeg kernel is gone.
// ---------------------------------------------------------------------------
#define APAD 12
#define BPAD 132

// Kernel 3: Y[bc] = (1/deg) * (adj[b] @ F[bc]), deg computed in-kernel
__global__ void __launch_bounds__(256) prop_kernel(const float* __restrict__ features) {
  __shared__ float As[2][128][APAD];
  __shared__ float Bs[2][8][BPAD];
  __shared__ float sinv[128];

  const int tid = threadIdx.x;
  const int bc = blockIdx.z;
  const int b  = bc >> 2;
  const int s0 = blockIdx.y * 128;
  const int d0 = blockIdx.x * 128;

  const float* A  = g_adj + (size_t)b * NS * NS;
  const float* Bm = features + (size_t)bc * NS * NDIN;

  const int ar = tid >> 1, ac = (tid & 1) << 2;
  const int brow = tid >> 5, bcol = (tid & 31) << 2;

  const int wid = tid >> 5, lane = tid & 31;
  const int wm = (wid >> 2) * 64, wn = (wid & 3) * 32;
  const int gid = lane >> 2, t4 = lane & 3;
  const bool degwarp = (wid & 3) == 0;   // warps 0 and 4 own rows wm..wm+63

  const uint32_t sa0 = smem_u32(&As[0][ar][ac]);
  const uint32_t sa1 = smem_u32(&As[1][ar][ac]);
  const uint32_t sb0 = smem_u32(&Bs[0][brow][bcol]);
  const uint32_t sb1 = smem_u32(&Bs[1][brow][bcol]);

  float c[4][4][4];
#pragma unroll
  for (int i = 0; i < 4; i++)
#pragma unroll
    for (int j = 0; j < 4; j++)
#pragma unroll
      for (int r = 0; r < 4; r++) c[i][j][r] = 0.f;

  float dsum0[4] = {0.f, 0.f, 0.f, 0.f};   // rows wm+i*16+gid
  float dsum1[4] = {0.f, 0.f, 0.f, 0.f};   // rows wm+i*16+gid+8

  // preload tile 0
  CP_ASYNC16(sa0, A  + (size_t)(s0 + ar) * NS + ac);
  CP_ASYNC16(sb0, Bm + (size_t)brow * NDIN + d0 + bcol);
  CP_COMMIT();
  CP_WAIT0();
  __syncthreads();

  const int NK = NS / 8;
  for (int kt = 0; kt < NK; kt++) {
    const int cur = kt & 1;
    if (kt + 1 < NK) {
      int k0 = (kt + 1) * 8;
      CP_ASYNC16(cur ? sa0 : sa1, A  + (size_t)(s0 + ar) * NS + k0 + ac);
      CP_ASYNC16(cur ? sb0 : sb1, Bm + (size_t)(k0 + brow) * NDIN + d0 + bcol);
      CP_COMMIT();
    }
    uint32_t afr[4][4], bfr[4][2];
#pragma unroll
    for (int i = 0; i < 4; i++) {
      int row = wm + i * 16 + gid;
      float f0 = As[cur][row][t4];
      float f1 = As[cur][row + 8][t4];
      float f2 = As[cur][row][t4 + 4];
      float f3 = As[cur][row + 8][t4 + 4];
      if (degwarp) { dsum0[i] += f0 + f2; dsum1[i] += f1 + f3; }
      afr[i][0] = to_tf32(f0);
      afr[i][1] = to_tf32(f1);
      afr[i][2] = to_tf32(f2);
      afr[i][3] = to_tf32(f3);
    }
#pragma unroll
    for (int j = 0; j < 4; j++) {
      int col = wn + j * 8 + gid;
      bfr[j][0] = to_tf32(Bs[cur][t4][col]);
      bfr[j][1] = to_tf32(Bs[cur][t4 + 4][col]);
    }
#pragma unroll
    for (int i = 0; i < 4; i++)
#pragma unroll
      for (int j = 0; j < 4; j++)
        mma_tf32(c[i][j], afr[i][0], afr[i][1], afr[i][2], afr[i][3],
                 bfr[j][0], bfr[j][1]);
    if (kt + 1 < NK) {
      CP_WAIT0();
      __syncthreads();
    }
  }

  // finish degrees: reduce the 4 lanes sharing a gid (lanes gid*4 + 0..3),
  // then lane t4==0 writes 1/deg for its two rows.
  if (degwarp) {
#pragma unroll
    for (int i = 0; i < 4; i++) {
      dsum0[i] += __shfl_xor_sync(0xFFFFFFFFu, dsum0[i], 1);
      dsum0[i] += __shfl_xor_sync(0xFFFFFFFFu, dsum0[i], 2);
      dsum1[i] += __shfl_xor_sync(0xFFFFFFFFu, dsum1[i], 1);
      dsum1[i] += __shfl_xor_sync(0xFFFFFFFFu, dsum1[i], 2);
      if (t4 == 0) {
        sinv[wm + i * 16 + gid]     = 1.0f / dsum0[i];
        sinv[wm + i * 16 + gid + 8] = 1.0f / dsum1[i];
      }
    }
  }
  __syncthreads();

#pragma unroll
  for (int i = 0; i < 4; i++) {
    int lr0 = wm + i * 16 + gid;
    int lr1 = lr0 + 8;
    float sc0 = sinv[lr0];
    float sc1 = sinv[lr1];
    int r0 = s0 + lr0, r1 = s0 + lr1;
#pragma unroll
    for (int j = 0; j < 4; j++) {
      int col = d0 + wn + j * 8 + 2 * t4;
      float* p0 = &g_Y[((size_t)bc * NS + r0) * NDIN + col];
      float* p1 = &g_Y[((size_t)bc * NS + r1) * NDIN + col];
      *reinterpret_cast<float2*>(p0) = make_float2(sc0 * c[i][j][0], sc0 * c[i][j][1]);
      *reinterpret_cast<float2*>(p1) = make_float2(sc1 * c[i][j][2], sc1 * c[i][j][3]);
    }
  }
}

// Kernel 4: out = Y @ Wl + bl   (32768 x 256 x 256, unchanged from R16)
__global__ void __launch_bounds__(256) out_kernel(const float* __restrict__ Wl,
                                                  const float* __restrict__ bl,
                                                  float* __restrict__ out) {
  __shared__ float As[2][128][APAD];
  __shared__ float Bs[2][8][BPAD];

  const int tid = threadIdx.x;
  const int m0 = blockIdx.y * 128;
  const int n0 = blockIdx.x * 128;

  const int ar = tid >> 1, ac = (tid & 1) << 2;
  const int brow = tid >> 5, bcol = (tid & 31) << 2;

  const int wid = tid >> 5, lane = tid & 31;
  const int wm = (wid >> 2) * 64, wn = (wid & 3) * 32;
  const int gid = lane >> 2, t4 = lane & 3;

  const uint32_t sa0 = smem_u32(&As[0][ar][ac]);
  const uint32_t sa1 = smem_u32(&As[1][ar][ac]);
  const uint32_t sb0 = smem_u32(&Bs[0][brow][bcol]);
  const uint32_t sb1 = smem_u32(&Bs[1][brow][bcol]);

  float c[4][4][4];
#pragma unroll
  for (int i = 0; i < 4; i++)
#pragma unroll
    for (int j = 0; j < 4; j++)
#pragma unroll
      for (int r = 0; r < 4; r++) c[i][j][r] = 0.f;

  CP_ASYNC16(sa0, g_Y + (size_t)(m0 + ar) * NDIN + ac);
  CP_ASYNC16(sb0, Wl + (size_t)brow * NDOUT + n0 + bcol);
  CP_COMMIT();
  CP_WAIT0();
  __syncthreads();

  const int NK = NDIN / 8;
  for (int kt = 0; kt < NK; kt++) {
    const int cur = kt & 1;
    if (kt + 1 < NK) {
      int k0 = (kt + 1) * 8;
      CP_ASYNC16(cur ? sa0 : sa1, g_Y + (size_t)(m0 + ar) * NDIN + k0 + ac);
      CP_ASYNC16(cur ? sb0 : sb1, Wl + (size_t)(k0 + brow) * NDOUT + n0 + bcol);
      CP_COMMIT();
    }
    uint32_t afr[4][4], bfr[4][2];
#pragma unroll
    for (int i = 0; i < 4; i++) {
      int row = wm + i * 16 + gid;
      afr[i][0] = to_tf32(As[cur][row][t4]);
      afr[i][1] = to_tf32(As[cur][row + 8][t4]);
      afr[i][2] = to_tf32(As[cur][row][t4 + 4]);
      afr[i][3] = to_tf32(As[cur][row + 8][t4 + 4]);
    }
#pragma unroll
    for (int j = 0; j < 4; j++) {
      int col = wn + j * 8 + gid;
      bfr[j][0] = to_tf32(Bs[cur][t4][col]);
      bfr[j][1] = to_tf32(Bs[cur][t4 + 4][col]);
    }
#pragma unroll
    for (int i = 0; i < 4; i++)
#pragma unroll
      for (int j = 0; j < 4; j++)
        mma_tf32(c[i][j], afr[i][0], afr[i][1], afr[i][2], afr[i][3],
                 bfr[j][0], bfr[j][1]);
    if (kt + 1 < NK) {
      CP_WAIT0();
      __syncthreads();
    }
  }

#pragma unroll
  for (int i = 0; i < 4; i++) {
    int r0 = m0 + wm + i * 16 + gid;
    int r1 = r0 + 8;
#pragma unroll
    for (int j = 0; j < 4; j++) {
      int col = n0 + wn + j * 8 + 2 * t4;
      float2 bias = *reinterpret_cast<const float2*>(bl + col);
      float* p0 = &out[(size_t)r0 * NDOUT + col];
      float* p1 = &out[(size_t)r1 * NDOUT + col];
      *reinterpret_cast<float2*>(p0) = make_float2(c[i][j][0] + bias.x, c[i][j][1] + bias.y);
      *reinterpret_cast<float2*>(p1) = make_float2(c[i][j][2] + bias.x, c[i][j][3] + bias.y);
    }
  }
}

// ---------------------------------------------------------------------------
extern "C" void kernel_launch(void* const* d_in, const int* in_sizes, int n_in,
                              void* d_out, int out_size) {
  const float *features = 0, *fm = 0, *W1 = 0, *b1 = 0, *W2 = 0, *b2 = 0,
              *W3 = 0, *b3 = 0, *Wl = 0, *bl = 0;
  int n16 = 0;
  for (int i = 0; i < n_in; i++) {
    const float* p = (const float*)d_in[i];
    switch (in_sizes[i]) {
      case 8388608: features = p; break;
      case 2097152: fm = p; break;
      case 128:     W2 = p; break;
      case 8:       b2 = p; break;
      case 2:       b3 = p; break;
      case 65536:   Wl = p; break;
      case 256:     bl = p; break;
      case 16:
        if (n16 == 0) W1 = p; else if (n16 == 1) b1 = p; else W3 = p;
        n16++; break;
      default: break;
    }
  }
  float* out = (float*)d_out;

  build_tab_kernel<<<(TAB_N + 256) / 256, 256>>>(W1, b1, W2, b2, W3, b3);
  adj_kernel<<<dim3(4, 4, 32), 256>>>(fm, W1, b1, W2, b2, W3, b3);
  prop_kernel<<<dim3(2, 2, 128), 256>>>(features);
  out_kernel<<<dim3(2, 256, 1), 256>>>(Wl, bl, out);
}